// round 4
// baseline (speedup 1.0000x reference)
#include <cuda_runtime.h>

// Fused GAT representation network, fp32x2 packed-FMA version.
// 4 graphs per 256-thread block; features stored transposed in shared:
// hT[item][feature][node] with row stride HS=20 floats.
// GEMM/aggregation thread mapping: u = t>>6 (item), v = t&63,
// thread owns columns 4v..4v+3 (all within head hq = v>>4).

#define NN 16
#define HS 20   // hT row stride in floats (multiple of 4)

// shared-memory float offsets
#define OFF_HT    0                     // [4][256][HS]
#define SZ_HT     (4 * 256 * HS)        // 20480
#define OFF_AL    (OFF_HT + SZ_HT)      // alpha [4][4][16][16]; also x staging
#define SZ_AL     (4 * 1024)
#define OFF_ES    (OFF_AL + SZ_AL)      // esrc [4][16][4]
#define OFF_ED    (OFF_ES + 256)        // edst [4][16][4]
#define OFF_G4    (OFF_ED + 256)        // per-head pooled sums [4][4][64]
#define OFF_G     (OFF_G4 + 1024)       // g [4][64]
#define OFF_Y     (OFF_G + 256)         // y [4][132]
#define OFF_RED   (OFF_Y + 4 * 132)     // LN partials [4][8]
#define SMEM_FLOATS (OFF_RED + 32)
#define SMEM_BYTES  (SMEM_FLOATS * 4)

typedef unsigned long long ull;

__device__ __forceinline__ ull pk(float lo, float hi) {
    ull r; asm("mov.b64 %0, {%1,%2};" : "=l"(r) : "f"(lo), "f"(hi)); return r;
}
__device__ __forceinline__ void upk(ull v, float& lo, float& hi) {
    asm("mov.b64 {%0,%1}, %2;" : "=f"(lo), "=f"(hi) : "l"(v));
}
__device__ __forceinline__ void ffma2(ull& d, ull a, ull b) {
    asm("fma.rn.f32x2 %0, %1, %2, %0;" : "+l"(d) : "l"(a), "l"(b));
}

__device__ __forceinline__ unsigned adjmask(int i) {
    int r = i >> 2, c = i & 3;
    unsigned m = 1u << i;
    if (c > 0) m |= 1u << (i - 1);
    if (c < 3) m |= 1u << (i + 1);
    if (r > 0) m |= 1u << (i - 4);
    if (r < 3) m |= 1u << (i + 4);
    return m;
}

template<int FIN, bool FINAL>
__device__ __forceinline__ void gat_layer(
    float* sm, int t, int u, int v,
    const float* __restrict__ W,
    const float* __restrict__ asrc,
    const float* __restrict__ adst,
    const float* __restrict__ bb)
{
    float* hTu = sm + OFF_HT + u * (256 * HS);
    const int c0 = 4 * v;
    const int hq = v >> 4;

    // ---- GEMM: wh[:, c0..c0+3] = h @ W, node pairs packed in f32x2 ----
    ull acc[4][8];
    #pragma unroll
    for (int c = 0; c < 4; c++)
        #pragma unroll
        for (int p = 0; p < 8; p++) acc[c][p] = 0ull;

    #pragma unroll 4
    for (int k = 0; k < FIN; k++) {
        float4 w4 = *(const float4*)&W[k * 256 + c0];
        ull wp0 = pk(w4.x, w4.x), wp1 = pk(w4.y, w4.y);
        ull wp2 = pk(w4.z, w4.z), wp3 = pk(w4.w, w4.w);
        const float* hr = &hTu[k * HS];
        float4 h0 = *(const float4*)&hr[0];
        float4 h1 = *(const float4*)&hr[4];
        float4 h2 = *(const float4*)&hr[8];
        float4 h3 = *(const float4*)&hr[12];
        ull hp[8] = { pk(h0.x,h0.y), pk(h0.z,h0.w), pk(h1.x,h1.y), pk(h1.z,h1.w),
                      pk(h2.x,h2.y), pk(h2.z,h2.w), pk(h3.x,h3.y), pk(h3.z,h3.w) };
        #pragma unroll
        for (int p = 0; p < 8; p++) {
            ffma2(acc[0][p], hp[p], wp0);
            ffma2(acc[1][p], hp[p], wp1);
            ffma2(acc[2][p], hp[p], wp2);
            ffma2(acc[3][p], hp[p], wp3);
        }
    }
    __syncthreads();   // everyone done reading hT
    #pragma unroll
    for (int c = 0; c < 4; c++) {
        #pragma unroll
        for (int p = 0; p < 8; p++) {
            float lo, hi; upk(acc[c][p], lo, hi);
            *(float2*)&hTu[(c0 + c) * HS + 2 * p] = make_float2(lo, hi);
        }
    }
    __syncthreads();

    // ---- logits: one thread per (u, n, hh) ----
    {
        int id = t & 63, n = id & 15, hh = id >> 4;
        float as = 0.f, ad = 0.f;
        #pragma unroll 8
        for (int c = 0; c < 64; c++) {
            float vv = hTu[(hh * 64 + c) * HS + n];
            as = fmaf(vv, asrc[hh * 64 + c], as);
            ad = fmaf(vv, adst[hh * 64 + c], ad);
        }
        sm[OFF_ES + u * 64 + n * 4 + hh] = as;
        sm[OFF_ED + u * 64 + n * 4 + hh] = ad;
    }
    __syncthreads();

    // ---- masked softmax: one thread per (u, i, hh); alpha stored j-major ----
    {
        int id = t & 63, i = id & 15, hh = id >> 4;
        unsigned m = adjmask(i);
        float ed = sm[OFF_ED + u * 64 + i * 4 + hh];
        float eb[NN];
        float mx = -1e30f;
        #pragma unroll
        for (int j = 0; j < NN; j++) {
            eb[j] = -1e30f;
            if ((m >> j) & 1u) {
                float e = ed + sm[OFF_ES + u * 64 + j * 4 + hh];
                e = e > 0.f ? e : 0.2f * e;
                eb[j] = e;
                mx = fmaxf(mx, e);
            }
        }
        float ssum = 0.f;
        #pragma unroll
        for (int j = 0; j < NN; j++) {
            float a = ((m >> j) & 1u) ? __expf(eb[j] - mx) : 0.f;
            eb[j] = a;
            ssum += a;
        }
        float inv = 1.f / ssum;
        #pragma unroll
        for (int j = 0; j < NN; j++)
            sm[OFF_AL + u * 1024 + hh * 256 + j * 16 + i] = eb[j] * inv;
    }
    __syncthreads();

    // ---- aggregation: out[i][c] = sum_j alpha[h][j][i] * wh[j][c] ----
    ull o2[4][8];
    #pragma unroll
    for (int c = 0; c < 4; c++)
        #pragma unroll
        for (int p = 0; p < 8; p++) o2[c][p] = 0ull;

    const float* au = sm + OFF_AL + u * 1024 + hq * 256;
    #pragma unroll
    for (int j = 0; j < NN; j++) {
        float4 a0 = *(const float4*)&au[j * 16 + 0];
        float4 a1 = *(const float4*)&au[j * 16 + 4];
        float4 a2 = *(const float4*)&au[j * 16 + 8];
        float4 a3 = *(const float4*)&au[j * 16 + 12];
        ull ap[8] = { pk(a0.x,a0.y), pk(a0.z,a0.w), pk(a1.x,a1.y), pk(a1.z,a1.w),
                      pk(a2.x,a2.y), pk(a2.z,a2.w), pk(a3.x,a3.y), pk(a3.z,a3.w) };
        #pragma unroll
        for (int c = 0; c < 4; c++) {
            float wv = hTu[(c0 + c) * HS + j];
            ull wp = pk(wv, wv);
            #pragma unroll
            for (int p = 0; p < 8; p++) ffma2(o2[c][p], ap[p], wp);
        }
    }
    __syncthreads();   // everyone done reading hT + alpha

    if (FINAL) {
        // pool over nodes now; cross-head sum after sync
        float cs[4];
        #pragma unroll
        for (int c = 0; c < 4; c++) {
            float s = 0.f;
            #pragma unroll
            for (int p = 0; p < 8; p++) {
                float lo, hi; upk(o2[c][p], lo, hi);
                s += lo + hi;
            }
            cs[c] = s;
        }
        *(float4*)&sm[OFF_G4 + u * 256 + hq * 64 + (c0 & 63)] =
            make_float4(cs[0], cs[1], cs[2], cs[3]);
    } else {
        float4 b4 = *(const float4*)&bb[c0];
        float bbv[4] = { b4.x, b4.y, b4.z, b4.w };
        #pragma unroll
        for (int c = 0; c < 4; c++) {
            #pragma unroll
            for (int p = 0; p < 8; p++) {
                float lo, hi; upk(o2[c][p], lo, hi);
                lo = fmaxf(lo + bbv[c], 0.f);
                hi = fmaxf(hi + bbv[c], 0.f);
                *(float2*)&hTu[(c0 + c) * HS + 2 * p] = make_float2(lo, hi);
            }
        }
    }
    __syncthreads();
}

__global__ void __launch_bounds__(256, 2) gat_fused_kernel(
    const float* __restrict__ x,
    const float* __restrict__ w_in, const float* __restrict__ b_in,
    const float* __restrict__ W0, const float* __restrict__ as0,
    const float* __restrict__ ad0, const float* __restrict__ bb0,
    const float* __restrict__ W1, const float* __restrict__ as1,
    const float* __restrict__ ad1, const float* __restrict__ bb1,
    const float* __restrict__ W2, const float* __restrict__ as2,
    const float* __restrict__ ad2, const float* __restrict__ bb2,
    const float* __restrict__ w1, const float* __restrict__ b1,
    const float* __restrict__ lng, const float* __restrict__ lnb,
    const float* __restrict__ w2, const float* __restrict__ b2,
    float* __restrict__ out)
{
    extern __shared__ float sm[];
    int t = threadIdx.x;
    int u = t >> 6;           // item
    int v = t & 63;
    long item0 = (long)blockIdx.x * 4;

    // ---- stage x (4 graphs * 256 floats) into alpha scratch ----
    #pragma unroll
    for (int q = 0; q < 4; q++)
        sm[OFF_AL + q * 1024 + t] = x[(item0 + q) * 256 + t];
    __syncthreads();

    // ---- input linear -> hT[f][n], one thread per (u, f) ----
    {
        int f = v;
        const float* xs = sm + OFF_AL + u * 1024;
        float* hTu = sm + OFF_HT + u * (256 * HS);
        float acc[NN];
        #pragma unroll
        for (int n = 0; n < NN; n++) acc[n] = 0.f;
        #pragma unroll
        for (int c = 0; c < 16; c++) {
            float wv = w_in[c * 64 + f];
            #pragma unroll
            for (int n = 0; n < NN; n++)
                acc[n] = fmaf(xs[c * 16 + n], wv, acc[n]);
        }
        float bv = b_in[f];
        #pragma unroll
        for (int n = 0; n < NN; n++)
            hTu[f * HS + n] = fmaxf(acc[n] + bv, 0.f);
    }
    __syncthreads();

    gat_layer<64,  false>(sm, t, u, v, W0, as0, ad0, bb0);
    gat_layer<256, false>(sm, t, u, v, W1, as1, ad1, bb1);
    gat_layer<256, true >(sm, t, u, v, W2, as2, ad2, bb2);

    // ---- cross-head pooled g[c], one thread per (u, c) ----
    {
        float sg = sm[OFF_G4 + u * 256 +   0 + v]
                 + sm[OFF_G4 + u * 256 +  64 + v]
                 + sm[OFF_G4 + u * 256 + 128 + v]
                 + sm[OFF_G4 + u * 256 + 192 + v];
        sm[OFF_G + u * 64 + v] = sg * (1.0f / 64.0f) + bb2[v];
    }
    __syncthreads();

    // ---- MLP layer 1 (64->128) + LayerNorm + relu; thread covers 2 items ----
    {
        int fy = t & 127, up = t >> 7;
        int ua = up, ub = up + 2;
        float va = b1[fy], vb = va;
        #pragma unroll 4
        for (int c = 0; c < 64; c += 4) {
            float4 ga = *(const float4*)&sm[OFF_G + ua * 64 + c];
            float4 gb = *(const float4*)&sm[OFF_G + ub * 64 + c];
            float w0 = w1[(c + 0) * 128 + fy];
            float wA = w1[(c + 1) * 128 + fy];
            float wB = w1[(c + 2) * 128 + fy];
            float wC = w1[(c + 3) * 128 + fy];
            va = fmaf(ga.x, w0, fmaf(ga.y, wA, fmaf(ga.z, wB, fmaf(ga.w, wC, va))));
            vb = fmaf(gb.x, w0, fmaf(gb.y, wA, fmaf(gb.z, wB, fmaf(gb.w, wC, vb))));
        }
        float sa = va, sb = vb;
        #pragma unroll
        for (int off = 16; off; off >>= 1) {
            sa += __shfl_xor_sync(0xffffffffu, sa, off);
            sb += __shfl_xor_sync(0xffffffffu, sb, off);
        }
        int wi = (t >> 5) & 3;
        if ((t & 31) == 0) {
            sm[OFF_RED + ua * 8 + wi] = sa;
            sm[OFF_RED + ub * 8 + wi] = sb;
        }
        __syncthreads();
        float mua = (sm[OFF_RED + ua * 8 + 0] + sm[OFF_RED + ua * 8 + 1] +
                     sm[OFF_RED + ua * 8 + 2] + sm[OFF_RED + ua * 8 + 3]) * (1.f / 128.f);
        float mub = (sm[OFF_RED + ub * 8 + 0] + sm[OFF_RED + ub * 8 + 1] +
                     sm[OFF_RED + ub * 8 + 2] + sm[OFF_RED + ub * 8 + 3]) * (1.f / 128.f);
        float da = va - mua, db = vb - mub;
        float qa = da * da, qb = db * db;
        #pragma unroll
        for (int off = 16; off; off >>= 1) {
            qa += __shfl_xor_sync(0xffffffffu, qa, off);
            qb += __shfl_xor_sync(0xffffffffu, qb, off);
        }
        if ((t & 31) == 0) {
            sm[OFF_RED + ua * 8 + 4 + wi] = qa;
            sm[OFF_RED + ub * 8 + 4 + wi] = qb;
        }
        __syncthreads();
        float vara = (sm[OFF_RED + ua * 8 + 4] + sm[OFF_RED + ua * 8 + 5] +
                      sm[OFF_RED + ua * 8 + 6] + sm[OFF_RED + ua * 8 + 7]) * (1.f / 128.f);
        float varb = (sm[OFF_RED + ub * 8 + 4] + sm[OFF_RED + ub * 8 + 5] +
                      sm[OFF_RED + ub * 8 + 6] + sm[OFF_RED + ub * 8 + 7]) * (1.f / 128.f);
        float gv = lng[fy], bv = lnb[fy];
        sm[OFF_Y + ua * 132 + fy] = fmaxf(da * rsqrtf(vara + 1e-5f) * gv + bv, 0.f);
        sm[OFF_Y + ub * 132 + fy] = fmaxf(db * rsqrtf(varb + 1e-5f) * gv + bv, 0.f);
    }
    __syncthreads();

    // ---- MLP layer 2 (128 -> 256), write 4 items ----
    {
        float a0 = b2[t], a1 = a0, a2 = a0, a3 = a0;
        #pragma unroll 4
        for (int f = 0; f < 128; f += 4) {
            float4 y0 = *(const float4*)&sm[OFF_Y + 0 * 132 + f];
            float4 y1 = *(const float4*)&sm[OFF_Y + 1 * 132 + f];
            float4 y2 = *(const float4*)&sm[OFF_Y + 2 * 132 + f];
            float4 y3 = *(const float4*)&sm[OFF_Y + 3 * 132 + f];
            float w0 = w2[(f + 0) * 256 + t];
            float wA = w2[(f + 1) * 256 + t];
            float wB = w2[(f + 2) * 256 + t];
            float wC = w2[(f + 3) * 256 + t];
            a0 = fmaf(y0.x, w0, fmaf(y0.y, wA, fmaf(y0.z, wB, fmaf(y0.w, wC, a0))));
            a1 = fmaf(y1.x, w0, fmaf(y1.y, wA, fmaf(y1.z, wB, fmaf(y1.w, wC, a1))));
            a2 = fmaf(y2.x, w0, fmaf(y2.y, wA, fmaf(y2.z, wB, fmaf(y2.w, wC, a2))));
            a3 = fmaf(y3.x, w0, fmaf(y3.y, wA, fmaf(y3.z, wB, fmaf(y3.w, wC, a3))));
        }
        out[(item0 + 0) * 256 + t] = a0;
        out[(item0 + 1) * 256 + t] = a1;
        out[(item0 + 2) * 256 + t] = a2;
        out[(item0 + 3) * 256 + t] = a3;
    }
}

extern "C" void kernel_launch(void* const* d_in, const int* in_sizes, int n_in,
                              void* d_out, int out_size)
{
    const float* x    = (const float*)d_in[0];
    const float* w_in = (const float*)d_in[1];
    const float* b_in = (const float*)d_in[2];
    const float* W0   = (const float*)d_in[3];
    const float* as0  = (const float*)d_in[4];
    const float* ad0  = (const float*)d_in[5];
    const float* bb0  = (const float*)d_in[6];
    const float* W1   = (const float*)d_in[7];
    const float* as1  = (const float*)d_in[8];
    const float* ad1  = (const float*)d_in[9];
    const float* bb1  = (const float*)d_in[10];
    const float* W2   = (const float*)d_in[11];
    const float* as2  = (const float*)d_in[12];
    const float* ad2  = (const float*)d_in[13];
    const float* bb2  = (const float*)d_in[14];
    const float* w1   = (const float*)d_in[15];
    const float* b1   = (const float*)d_in[16];
    const float* lng  = (const float*)d_in[17];
    const float* lnb  = (const float*)d_in[18];
    const float* w2   = (const float*)d_in[19];
    const float* b2   = (const float*)d_in[20];
    float* out = (float*)d_out;

    int B = out_size / 256;       // 16384
    int grid = B / 4;             // 4 graphs per block

    cudaFuncSetAttribute(gat_fused_kernel,
                         cudaFuncAttributeMaxDynamicSharedMemorySize, SMEM_BYTES);
    gat_fused_kernel<<<grid, 256, SMEM_BYTES>>>(
        x, w_in, b_in,
        W0, as0, ad0, bb0,
        W1, as1, ad1, bb1,
        W2, as2, ad2, bb2,
        w1, b1, lng, lnb, w2, b2,
        out);
}

// round 6
// speedup vs baseline: 1.6629x; 1.6629x over previous
#include <cuda_runtime.h>
#include <cuda_fp16.h>
#include <cstdint>

// Fused GAT network on mma.sync.m16n8k16 (fp16 hi/lo, fp32 accum).
// 8 graphs per 512-thread block: M = 128 rows, N = 256, K = FIN.

#define NN 16
#define WSTR 264          // whbuf stride (floats)
#define ASTRB 528         // A row stride bytes (264 halves)
#define BSTRB 144         // B chunk row stride bytes (72 halves)

// ---- shared memory byte offsets ----
#define OFF_AH    0            // fp16 hi A tile 128 x 264 (67584 B)
#define OFF_AL    67584        // fp16 lo A tile
#define OFF_WHB   0            // fp32 whbuf 128 x 264 overlays A (135168 B)
#define OFF_BH    135168       // fp16 hi B chunk 256 x 72 (36864 B)
#define OFF_BL    172032       // fp16 lo B chunk
#define OFF_XS    135168       // x staging (8192 B) overlays B, pre-layer0
#define OFF_ALPHA 135168       // 32768 B overlays B_hi after GEMM
#define OFF_ES    172032       // 2048 B overlays B_lo after GEMM
#define OFF_ED    174080       // 2048 B
#define OFF_G4    208896       // 8192 B
#define OFF_G     217088       // 2048 B
#define OFF_Y     219136       // 4224 B
#define OFF_RED   223360       // 256 B
#define SMEM_BYTES 223616

// split transposed weights WT[n][k] fp16: W0 16384, W1 65536, W2 65536 elems
__device__ __align__(16) __half g_WTh[147456];
__device__ __align__(16) __half g_WTl[147456];

typedef unsigned long long ull;

__device__ __forceinline__ uint32_t smem_u32(const void* p) {
    uint32_t a;
    asm("{ .reg .u64 t; cvta.to.shared.u64 t, %1; cvt.u32.u64 %0, t; }" : "=r"(a) : "l"(p));
    return a;
}

#define LDSM4(r, a) \
    asm volatile("ldmatrix.sync.aligned.m8n8.x4.shared.b16 {%0,%1,%2,%3}, [%4];" \
        : "=r"((r)[0]), "=r"((r)[1]), "=r"((r)[2]), "=r"((r)[3]) : "r"(a))

#define MMA16816(d, a, b0, b1) \
    asm volatile("mma.sync.aligned.m16n8k16.row.col.f32.f16.f16.f32 " \
        "{%0,%1,%2,%3}, {%4,%5,%6,%7}, {%8,%9}, {%0,%1,%2,%3};" \
        : "+f"((d)[0]), "+f"((d)[1]), "+f"((d)[2]), "+f"((d)[3]) \
        : "r"((a)[0]), "r"((a)[1]), "r"((a)[2]), "r"((a)[3]), "r"(b0), "r"(b1))

__device__ __forceinline__ ull pk(float lo, float hi) {
    ull r; asm("mov.b64 %0, {%1,%2};" : "=l"(r) : "f"(lo), "f"(hi)); return r;
}
__device__ __forceinline__ void upk(ull v, float& lo, float& hi) {
    asm("mov.b64 {%0,%1}, %2;" : "=f"(lo), "=f"(hi) : "l"(v));
}
__device__ __forceinline__ void ffma2(ull& d, ull a, ull b) {
    asm("fma.rn.f32x2 %0, %1, %2, %0;" : "+l"(d) : "l"(a), "l"(b));
}

__device__ __forceinline__ unsigned adjmask(int i) {
    int r = i >> 2, c = i & 3;
    unsigned m = 1u << i;
    if (c > 0) m |= 1u << (i - 1);
    if (c < 3) m |= 1u << (i + 1);
    if (r > 0) m |= 1u << (i - 4);
    if (r < 3) m |= 1u << (i + 4);
    return m;
}

// ---- weight prep: transpose + fp16 hi/lo split ----
__global__ void prep_kernel(const float* __restrict__ W0,
                            const float* __restrict__ W1,
                            const float* __restrict__ W2) {
    int i = blockIdx.x * 256 + threadIdx.x;
    if (i >= 147456) return;
    float v;
    if (i < 16384) {                       // WT0[n*64+k] = W0[k*256+n]
        int n = i >> 6, k = i & 63;
        v = W0[k * 256 + n];
    } else if (i < 81920) {                // WT1[n*256+k] = W1[k*256+n]
        int j = i - 16384; int n = j >> 8, k = j & 255;
        v = W1[k * 256 + n];
    } else {                               // WT2
        int j = i - 81920; int n = j >> 8, k = j & 255;
        v = W2[k * 256 + n];
    }
    __half h = __float2half_rn(v);
    g_WTh[i] = h;
    g_WTl[i] = __float2half_rn(v - __half2float(h));
}

// ---- one GAT layer ----
template<int FIN, bool FINAL>
__device__ void gat_layer(char* smc, uint32_t smb, int tid,
                          const __half* __restrict__ WTh,
                          const __half* __restrict__ WTl,
                          const float* __restrict__ asrc,
                          const float* __restrict__ adst,
                          const float* __restrict__ bb)
{
    const int NCH = FIN / 64;
    const int wid = tid >> 5, l = tid & 31;
    const int wr = wid & 7;          // row group: rows 16wr..16wr+15
    const int cg = wid >> 3;         // col group: cols 128cg..128cg+127
    const int nb0 = cg * 128;

    // ldmatrix lane addresses
    uint32_t aAddrH = smb + OFF_AH + (uint32_t)((wr * 16 + (l & 15)) * ASTRB)
                    + (uint32_t)((l >> 4) * 16);
    uint32_t aAddrL = aAddrH + (OFF_AL - OFF_AH);
    int bn = (l & 7) + ((l >> 4) << 3);
    uint32_t bBase = smb + OFF_BH + (uint32_t)((nb0 + bn) * BSTRB)
                   + (uint32_t)(((l >> 3) & 1) * 16);

    float d[16][4];
    #pragma unroll
    for (int nb = 0; nb < 16; nb++)
        #pragma unroll
        for (int q = 0; q < 4; q++) d[nb][q] = 0.f;

    for (int kc = 0; kc < NCH; kc++) {
        // stage B chunk (256 rows x 64 halves, hi+lo)
        {
            int n = tid >> 1, hf2 = tid & 1;
            const uint4* sh = (const uint4*)(WTh + n * FIN + kc * 64 + hf2 * 32);
            const uint4* sl = (const uint4*)(WTl + n * FIN + kc * 64 + hf2 * 32);
            uint4* dh = (uint4*)(smc + OFF_BH + n * BSTRB + hf2 * 64);
            uint4* dl = (uint4*)(smc + OFF_BL + n * BSTRB + hf2 * 64);
            #pragma unroll
            for (int q = 0; q < 4; q++) { dh[q] = sh[q]; dl[q] = sl[q]; }
        }
        __syncthreads();
        #pragma unroll
        for (int kk = 0; kk < 4; kk++) {
            int k16 = kc * 4 + kk;
            uint32_t ah[4], al4[4];
            LDSM4(ah, aAddrH + k16 * 32);
            LDSM4(al4, aAddrL + k16 * 32);
            #pragma unroll
            for (int nc = 0; nc < 8; nc++) {
                uint32_t ba = bBase + nc * (16 * BSTRB) + kk * 32;
                uint32_t bh4[4], bl4[4];
                LDSM4(bh4, ba);
                LDSM4(bl4, ba + (OFF_BL - OFF_BH));
                MMA16816(d[2 * nc],     ah,  bh4[0], bh4[1]);
                MMA16816(d[2 * nc],     al4, bh4[0], bh4[1]);
                MMA16816(d[2 * nc],     ah,  bl4[0], bl4[1]);
                MMA16816(d[2 * nc + 1], ah,  bh4[2], bh4[3]);
                MMA16816(d[2 * nc + 1], al4, bh4[2], bh4[3]);
                MMA16816(d[2 * nc + 1], ah,  bl4[2], bl4[3]);
            }
        }
        __syncthreads();   // chunk reads done (also: A reads done after last chunk)
    }

    // ---- spill D -> whbuf (fp32, stride WSTR) ----
    {
        float* whb = (float*)(smc + OFF_WHB);
        int drow = wr * 16 + (l >> 2);
        int dcol = nb0 + (l & 3) * 2;
        #pragma unroll
        for (int nb = 0; nb < 16; nb++) {
            int cb = dcol + nb * 8;
            *(float2*)&whb[drow * WSTR + cb]       = make_float2(d[nb][0], d[nb][1]);
            *(float2*)&whb[(drow + 8) * WSTR + cb] = make_float2(d[nb][2], d[nb][3]);
        }
    }
    __syncthreads();

    // ---- logits: one thread per (u, n, h) ----
    {
        int u = tid >> 6, rem = tid & 63, n = rem & 15, hh = rem >> 4;
        const float* whr = (const float*)(smc + OFF_WHB) + (u * 16 + n) * WSTR + hh * 64;
        const float* ap_ = asrc + hh * 64;
        const float* dp_ = adst + hh * 64;
        float as = 0.f, ad = 0.f;
        #pragma unroll
        for (int c = 0; c < 64; c += 4) {
            float4 v = *(const float4*)&whr[c];
            float4 av = *(const float4*)&ap_[c];
            float4 dv = *(const float4*)&dp_[c];
            as = fmaf(v.x, av.x, fmaf(v.y, av.y, fmaf(v.z, av.z, fmaf(v.w, av.w, as))));
            ad = fmaf(v.x, dv.x, fmaf(v.y, dv.y, fmaf(v.z, dv.z, fmaf(v.w, dv.w, ad))));
        }
        ((float*)(smc + OFF_ES))[u * 64 + n * 4 + hh] = as;
        ((float*)(smc + OFF_ED))[u * 64 + n * 4 + hh] = ad;
    }
    __syncthreads();

    // ---- masked softmax: one thread per (u, i, hh) ----
    {
        int u = tid >> 6, rem = tid & 63, i = rem & 15, hh = rem >> 4;
        const float* es = (const float*)(smc + OFF_ES);
        const float* edp = (const float*)(smc + OFF_ED);
        unsigned m = adjmask(i);
        float ed = edp[u * 64 + i * 4 + hh];
        float eb[NN];
        float mx = -1e30f;
        #pragma unroll
        for (int j = 0; j < NN; j++) {
            eb[j] = -1e30f;
            if ((m >> j) & 1u) {
                float e = ed + es[u * 64 + j * 4 + hh];
                e = e > 0.f ? e : 0.2f * e;
                eb[j] = e;
                mx = fmaxf(mx, e);
            }
        }
        float ssum = 0.f;
        #pragma unroll
        for (int j = 0; j < NN; j++) {
            float a = ((m >> j) & 1u) ? __expf(eb[j] - mx) : 0.f;
            eb[j] = a;
            ssum += a;
        }
        float inv = 1.f / ssum;
        float* al = (float*)(smc + OFF_ALPHA);
        #pragma unroll
        for (int j = 0; j < NN; j++)
            al[u * 1024 + hh * 256 + j * 16 + i] = eb[j] * inv;
    }
    __syncthreads();

    // ---- aggregation: thread (ua, v) -> cols c0..c0+3, f32x2 packed ----
    int ua = tid >> 6, v = tid & 63, c0 = 4 * v, hq = v >> 4;
    ull o2[4][8];
    #pragma unroll
    for (int c = 0; c < 4; c++)
        #pragma unroll
        for (int p = 0; p < 8; p++) o2[c][p] = 0ull;
    {
        const float* au = (const float*)(smc + OFF_ALPHA) + ua * 1024 + hq * 256;
        const float* whu = (const float*)(smc + OFF_WHB) + ua * 16 * WSTR;
        #pragma unroll
        for (int j = 0; j < NN; j++) {
            float4 wv = *(const float4*)&whu[j * WSTR + c0];
            float4 a0 = *(const float4*)&au[j * 16 + 0];
            float4 a1 = *(const float4*)&au[j * 16 + 4];
            float4 a2 = *(const float4*)&au[j * 16 + 8];
            float4 a3 = *(const float4*)&au[j * 16 + 12];
            ull ap[8] = { pk(a0.x,a0.y), pk(a0.z,a0.w), pk(a1.x,a1.y), pk(a1.z,a1.w),
                          pk(a2.x,a2.y), pk(a2.z,a2.w), pk(a3.x,a3.y), pk(a3.z,a3.w) };
            ull wp0 = pk(wv.x, wv.x), wp1 = pk(wv.y, wv.y);
            ull wp2 = pk(wv.z, wv.z), wp3 = pk(wv.w, wv.w);
            #pragma unroll
            for (int p = 0; p < 8; p++) {
                ffma2(o2[0][p], ap[p], wp0);
                ffma2(o2[1][p], ap[p], wp1);
                ffma2(o2[2][p], ap[p], wp2);
                ffma2(o2[3][p], ap[p], wp3);
            }
        }
    }
    __syncthreads();   // whbuf/alpha reads done before overwriting A region

    if (FINAL) {
        float cs[4];
        #pragma unroll
        for (int c = 0; c < 4; c++) {
            float s = 0.f;
            #pragma unroll
            for (int p = 0; p < 8; p++) {
                float lo, hi; upk(o2[c][p], lo, hi);
                s += lo + hi;
            }
            cs[c] = s;
        }
        *(float4*)((float*)(smc + OFF_G4) + ua * 256 + hq * 64 + (c0 & 63)) =
            make_float4(cs[0], cs[1], cs[2], cs[3]);
        __syncthreads();
    } else {
        float4 b4 = *(const float4*)&bb[c0];
        float bbv[4] = { b4.x, b4.y, b4.z, b4.w };
        #pragma unroll
        for (int p = 0; p < 8; p++) {
            float va[4], vb[4];
            #pragma unroll
            for (int c = 0; c < 4; c++) {
                upk(o2[c][p], va[c], vb[c]);
                va[c] = fmaxf(va[c] + bbv[c], 0.f);
                vb[c] = fmaxf(vb[c] + bbv[c], 0.f);
            }
            #pragma unroll
            for (int hf = 0; hf < 2; hf++) {
                const float* src = hf ? vb : va;
                int rowg = ua * 16 + 2 * p + hf;
                unsigned hx[4], lx[4];
                #pragma unroll
                for (int c = 0; c < 4; c++) {
                    float vv = src[c];
                    __half bh = __float2half_rn(vv);
                    __half bl = __float2half_rn(vv - __half2float(bh));
                    hx[c] = (unsigned)__half_as_ushort(bh);
                    lx[c] = (unsigned)__half_as_ushort(bl);
                }
                uint2 ph2, pl2;
                ph2.x = (hx[1] << 16) | hx[0];  ph2.y = (hx[3] << 16) | hx[2];
                pl2.x = (lx[1] << 16) | lx[0];  pl2.y = (lx[3] << 16) | lx[2];
                *(uint2*)(smc + OFF_AH + rowg * ASTRB + c0 * 2) = ph2;
                *(uint2*)(smc + OFF_AL + rowg * ASTRB + c0 * 2) = pl2;
            }
        }
        __syncthreads();
    }
}

__global__ void __launch_bounds__(512, 1) gat_mma_kernel(
    const float* __restrict__ x,
    const float* __restrict__ w_in, const float* __restrict__ b_in,
    const float* __restrict__ as0, const float* __restrict__ ad0,
    const float* __restrict__ bb0,
    const float* __restrict__ as1, const float* __restrict__ ad1,
    const float* __restrict__ bb1,
    const float* __restrict__ as2, const float* __restrict__ ad2,
    const float* __restrict__ bb2,
    const float* __restrict__ w1, const float* __restrict__ b1,
    const float* __restrict__ lng, const float* __restrict__ lnb,
    const float* __restrict__ w2, const float* __restrict__ b2,
    float* __restrict__ out)
{
    extern __shared__ char smc[];
    uint32_t smb = smem_u32(smc);
    int tid = threadIdx.x;
    long item0 = (long)blockIdx.x * 8;

    // stage x: 8 items * 256 floats into (pre-layer0-dead) B region
    float* xs = (float*)(smc + OFF_XS);
    #pragma unroll
    for (int q = 0; q < 4; q++)
        xs[q * 512 + tid] = x[item0 * 256 + q * 512 + tid];
    __syncthreads();

    // input linear -> A (fp16 hi/lo), thread = (u = tid>>6, f = tid&63)
    {
        int u = tid >> 6, f = tid & 63;
        const float* xu = xs + u * 256;
        float acc[NN];
        #pragma unroll
        for (int nn = 0; nn < NN; nn++) acc[nn] = 0.f;
        #pragma unroll
        for (int c = 0; c < 16; c++) {
            float wv = w_in[c * 64 + f];
            #pragma unroll
            for (int nn = 0; nn < NN; nn++)
                acc[nn] = fmaf(xu[c * 16 + nn], wv, acc[nn]);
        }
        float bv = b_in[f];
        #pragma unroll
        for (int nn = 0; nn < NN; nn++) {
            float vv = fmaxf(acc[nn] + bv, 0.f);
            __half bh = __float2half_rn(vv);
            __half bl = __float2half_rn(vv - __half2float(bh));
            int row = u * 16 + nn;
            *(__half*)(smc + OFF_AH + row * ASTRB + f * 2) = bh;
            *(__half*)(smc + OFF_AL + row * ASTRB + f * 2) = bl;
        }
    }
    __syncthreads();

    gat_layer<64,  false>(smc, smb, tid, g_WTh,         g_WTl,         as0, ad0, bb0);
    gat_layer<256, false>(smc, smb, tid, g_WTh + 16384, g_WTl + 16384, as1, ad1, bb1);
    gat_layer<256, true >(smc, smb, tid, g_WTh + 81920, g_WTl + 81920, as2, ad2, bb2);

    // pooled g[c] = mean over nodes+heads + bb2
    {
        int u = tid >> 6, cc = tid & 63;
        const float* g4 = (const float*)(smc + OFF_G4) + u * 256;
        float sg = g4[cc] + g4[64 + cc] + g4[128 + cc] + g4[192 + cc];
        ((float*)(smc + OFF_G))[u * 64 + cc] = sg * (1.0f / 64.0f) + bb2[cc];
    }
    __syncthreads();

    // MLP1 (64->128) + LN + relu; thread covers items up, up+4
    {
        int fy = tid & 127, up = tid >> 7;
        int ua = up, ub = up + 4;
        const float* ga_ = (const float*)(smc + OFF_G) + ua * 64;
        const float* gb_ = (const float*)(smc + OFF_G) + ub * 64;
        float va = b1[fy], vb = va;
        #pragma unroll 4
        for (int c = 0; c < 64; c += 4) {
            float4 ga = *(const float4*)&ga_[c];
            float4 gb = *(const float4*)&gb_[c];
            float w0 = w1[(c + 0) * 128 + fy];
            float wA = w1[(c + 1) * 128 + fy];
            float wB = w1[(c + 2) * 128 + fy];
            float wC = w1[(c + 3) * 128 + fy];
            va = fmaf(ga.x, w0, fmaf(ga.y, wA, fmaf(ga.z, wB, fmaf(ga.w, wC, va))));
            vb = fmaf(gb.x, w0, fmaf(gb.y, wA, fmaf(gb.z, wB, fmaf(gb.w, wC, vb))));
        }
        float* red = (float*)(smc + OFF_RED);
        float sa = va, sb = vb;
        #pragma unroll
        for (int off = 16; off; off >>= 1) {
            sa += __shfl_xor_sync(0xffffffffu, sa, off);
            sb += __shfl_xor_sync(0xffffffffu, sb, off);
        }
        int wi = (tid >> 5) & 3;
        if ((tid & 31) == 0) { red[ua * 8 + wi] = sa; red[ub * 8 + wi] = sb; }
        __syncthreads();
        float mua = (red[ua * 8] + red[ua * 8 + 1] + red[ua * 8 + 2] + red[ua * 8 + 3]) * (1.f / 128.f);
        float mub = (red[ub * 8] + red[ub * 8 + 1] + red[ub * 8 + 2] + red[ub * 8 + 3]) * (1.f / 128.f);
        float da = va - mua, db = vb - mub;
        float qa = da * da, qb = db * db;
        #pragma unroll
        for (int off = 16; off; off >>= 1) {
            qa += __shfl_xor_sync(0xffffffffu, qa, off);
            qb += __shfl_xor_sync(0xffffffffu, qb, off);
        }
        if ((tid & 31) == 0) { red[ua * 8 + 4 + wi] = qa; red[ub * 8 + 4 + wi] = qb; }
        __syncthreads();
        float vara = (red[ua * 8 + 4] + red[ua * 8 + 5] + red[ua * 8 + 6] + red[ua * 8 + 7]) * (1.f / 128.f);
        float varb = (red[ub * 8 + 4] + red[ub * 8 + 5] + red[ub * 8 + 6] + red[ub * 8 + 7]) * (1.f / 128.f);
        float gv = lng[fy], bv = lnb[fy];
        float* yv = (float*)(smc + OFF_Y);
        yv[ua * 132 + fy] = fmaxf(da * rsqrtf(vara + 1e-5f) * gv + bv, 0.f);
        yv[ub * 132 + fy] = fmaxf(db * rsqrtf(varb + 1e-5f) * gv + bv, 0.f);
    }
    __syncthreads();

    // MLP2 (128->256): thread = (pr = tid>>8 -> items 4pr..4pr+3, col = tid&255)
    {
        int col = tid & 255, pr = tid >> 8;
        const float* yv = (const float*)(smc + OFF_Y) + pr * 4 * 132;
        float a0 = b2[col], a1 = a0, a2 = a0, a3 = a0;
        #pragma unroll 4
        for (int f = 0; f < 128; f += 4) {
            float4 y0 = *(const float4*)&yv[0 * 132 + f];
            float4 y1 = *(const float4*)&yv[1 * 132 + f];
            float4 y2 = *(const float4*)&yv[2 * 132 + f];
            float4 y3 = *(const float4*)&yv[3 * 132 + f];
            float w0 = w2[(f + 0) * 256 + col];
            float wA = w2[(f + 1) * 256 + col];
            float wB = w2[(f + 2) * 256 + col];
            float wC = w2[(f + 3) * 256 + col];
            a0 = fmaf(y0.x, w0, fmaf(y0.y, wA, fmaf(y0.z, wB, fmaf(y0.w, wC, a0))));
            a1 = fmaf(y1.x, w0, fmaf(y1.y, wA, fmaf(y1.z, wB, fmaf(y1.w, wC, a1))));
            a2 = fmaf(y2.x, w0, fmaf(y2.y, wA, fmaf(y2.z, wB, fmaf(y2.w, wC, a2))));
            a3 = fmaf(y3.x, w0, fmaf(y3.y, wA, fmaf(y3.z, wB, fmaf(y3.w, wC, a3))));
        }
        out[(item0 + 4 * pr + 0) * 256 + col] = a0;
        out[(item0 + 4 * pr + 1) * 256 + col] = a1;
        out[(item0 + 4 * pr + 2) * 256 + col] = a2;
        out[(item0 + 4 * pr + 3) * 256 + col] = a3;
    }
}

extern "C" void kernel_launch(void* const* d_in, const int* in_sizes, int n_in,
                              void* d_out, int out_size)
{
    const float* x    = (const float*)d_in[0];
    const float* w_in = (const float*)d_in[1];
    const float* b_in = (const float*)d_in[2];
    const float* W0   = (const float*)d_in[3];
    const float* as0  = (const float*)d_in[4];
    const float* ad0  = (const float*)d_in[5];
    const float* bb0  = (const float*)d_in[6];
    const float* W1   = (const float*)d_in[7];
    const float* as1  = (const float*)d_in[8];
    const float* ad1  = (const float*)d_in[9];
    const float* bb1  = (const float*)d_in[10];
    const float* W2   = (const float*)d_in[11];
    const float* as2  = (const float*)d_in[12];
    const float* ad2  = (const float*)d_in[13];
    const float* bb2  = (const float*)d_in[14];
    const float* w1   = (const float*)d_in[15];
    const float* b1   = (const float*)d_in[16];
    const float* lng  = (const float*)d_in[17];
    const float* lnb  = (const float*)d_in[18];
    const float* w2   = (const float*)d_in[19];
    const float* b2   = (const float*)d_in[20];
    float* out = (float*)d_out;

    int B = out_size / 256;        // 16384
    int grid = B / 8;              // 8 graphs per block

    prep_kernel<<<576, 256>>>(W0, W1, W2);

    cudaFuncSetAttribute(gat_mma_kernel,
                         cudaFuncAttributeMaxDynamicSharedMemorySize, SMEM_BYTES);
    gat_mma_kernel<<<grid, 512, SMEM_BYTES>>>(
        x, w_in, b_in,
        as0, ad0, bb0, as1, ad1, bb1, as2, ad2, bb2,
        w1, b1, lng, lnb, w2, b2, out);
}

// round 7
// speedup vs baseline: 2.2326x; 1.3426x over previous
#include <cuda_runtime.h>
#include <cuda_fp16.h>
#include <cstdint>

// Fused GAT network on mma.sync.m16n8k16 (A fp16 hi/lo, B fp16 hi only,
// fp32 accum). 8 graphs per 512-thread block: M = 128, N = 256, K = FIN.
// B chunks double-buffered so LDG overlaps MMA.

#define NN 16
#define WSTR 264          // whbuf stride (floats)
#define ASTRB 528         // A row stride bytes (264 halves)
#define BSTRB 144         // B chunk row stride bytes (72 halves)

// ---- shared memory byte offsets ----
#define OFF_AH    0            // fp16 hi A tile 128 x 264 (67584 B)
#define OFF_AL    67584        // fp16 lo A tile
#define OFF_WHB   0            // fp32 whbuf 128 x 264 overlays A (135168 B)
#define OFF_B0    135168       // fp16 B chunk buffer 0: 256 x 72 (36864 B)
#define OFF_B1    172032       // buffer 1
#define OFF_XS    135168       // x staging (8192 B) overlays B0, pre-layer0
#define OFF_ALPHA 135168       // 32768 B overlays B0 after GEMM
#define OFF_ES    167936       // 2048 B
#define OFF_ED    169984       // 2048 B
#define OFF_G4    208896       // 8192 B
#define OFF_G     217088       // 2048 B
#define OFF_Y     219136       // 4224 B
#define OFF_RED   223360       // 256 B
#define SMEM_BYTES 223616

// transposed fp16 weights WT[n][k]: W0 16384, W1 65536, W2 65536 elems
__device__ __align__(16) __half g_WTh[147456];

typedef unsigned long long ull;

__device__ __forceinline__ uint32_t smem_u32(const void* p) {
    uint32_t a;
    asm("{ .reg .u64 t; cvta.to.shared.u64 t, %1; cvt.u32.u64 %0, t; }" : "=r"(a) : "l"(p));
    return a;
}

#define LDSM4(r, a) \
    asm volatile("ldmatrix.sync.aligned.m8n8.x4.shared.b16 {%0,%1,%2,%3}, [%4];" \
        : "=r"((r)[0]), "=r"((r)[1]), "=r"((r)[2]), "=r"((r)[3]) : "r"(a))

#define MMA16816(d, a, b0, b1) \
    asm volatile("mma.sync.aligned.m16n8k16.row.col.f32.f16.f16.f32 " \
        "{%0,%1,%2,%3}, {%4,%5,%6,%7}, {%8,%9}, {%0,%1,%2,%3};" \
        : "+f"((d)[0]), "+f"((d)[1]), "+f"((d)[2]), "+f"((d)[3]) \
        : "r"((a)[0]), "r"((a)[1]), "r"((a)[2]), "r"((a)[3]), "r"(b0), "r"(b1))

__device__ __forceinline__ ull pk(float lo, float hi) {
    ull r; asm("mov.b64 %0, {%1,%2};" : "=l"(r) : "f"(lo), "f"(hi)); return r;
}
__device__ __forceinline__ void upk(ull v, float& lo, float& hi) {
    asm("mov.b64 {%0,%1}, %2;" : "=f"(lo), "=f"(hi) : "l"(v));
}
__device__ __forceinline__ void ffma2(ull& d, ull a, ull b) {
    asm("fma.rn.f32x2 %0, %1, %2, %0;" : "+l"(d) : "l"(a), "l"(b));
}

__device__ __forceinline__ unsigned adjmask(int i) {
    int r = i >> 2, c = i & 3;
    unsigned m = 1u << i;
    if (c > 0) m |= 1u << (i - 1);
    if (c < 3) m |= 1u << (i + 1);
    if (r > 0) m |= 1u << (i - 4);
    if (r < 3) m |= 1u << (i + 4);
    return m;
}

// ---- weight prep: transpose + fp16 ----
__global__ void prep_kernel(const float* __restrict__ W0,
                            const float* __restrict__ W1,
                            const float* __restrict__ W2) {
    int i = blockIdx.x * 256 + threadIdx.x;
    if (i >= 147456) return;
    float v;
    if (i < 16384) {                       // WT0[n*64+k] = W0[k*256+n]
        int n = i >> 6, k = i & 63;
        v = W0[k * 256 + n];
    } else if (i < 81920) {                // WT1[n*256+k] = W1[k*256+n]
        int j = i - 16384; int n = j >> 8, k = j & 255;
        v = W1[k * 256 + n];
    } else {                               // WT2
        int j = i - 81920; int n = j >> 8, k = j & 255;
        v = W2[k * 256 + n];
    }
    g_WTh[i] = __float2half_rn(v);
}

// ---- one GAT layer ----
template<int FIN, bool FINAL>
__device__ void gat_layer(char* smc, uint32_t smb, int tid,
                          const __half* __restrict__ WTh,
                          const float* __restrict__ asrc,
                          const float* __restrict__ adst,
                          const float* __restrict__ bb)
{
    const int NCH = FIN / 64;
    const int wid = tid >> 5, l = tid & 31;
    const int wr = wid & 7;          // row group: rows 16wr..16wr+15
    const int cg = wid >> 3;         // col group: cols 128cg..128cg+127
    const int nb0 = cg * 128;

    // ldmatrix lane addresses for A
    uint32_t aAddrH = smb + OFF_AH + (uint32_t)((wr * 16 + (l & 15)) * ASTRB)
                    + (uint32_t)((l >> 4) * 16);
    uint32_t aAddrL = aAddrH + (OFF_AL - OFF_AH);
    // B lane-invariant offset within a chunk buffer
    int bn = (l & 7) + ((l >> 4) << 3);
    uint32_t bLane = (uint32_t)((nb0 + bn) * BSTRB) + (uint32_t)(((l >> 3) & 1) * 16);

    // B staging mapping: thread -> 64 contiguous bytes (4 x uint4)
    const int sn = tid >> 1, shf = tid & 1;
    const uint4* gsrc = (const uint4*)(WTh + sn * FIN + shf * 32);
    uint4* sdst0 = (uint4*)(smc + OFF_B0 + sn * BSTRB + shf * 64);
    uint4* sdst1 = (uint4*)(smc + OFF_B1 + sn * BSTRB + shf * 64);

    float d[16][4];
    #pragma unroll
    for (int nb = 0; nb < 16; nb++)
        #pragma unroll
        for (int q = 0; q < 4; q++) d[nb][q] = 0.f;

    // prologue: stage chunk 0 into B0
    {
        uint4 r[4];
        #pragma unroll
        for (int q = 0; q < 4; q++) r[q] = gsrc[q];
        #pragma unroll
        for (int q = 0; q < 4; q++) sdst0[q] = r[q];
    }
    __syncthreads();

    for (int kc = 0; kc < NCH; kc++) {
        uint4 rnext[4];
        if (kc + 1 < NCH) {
            #pragma unroll
            for (int q = 0; q < 4; q++) rnext[q] = gsrc[(kc + 1) * 8 + q];
        }
        uint32_t bufBase = smb + ((kc & 1) ? OFF_B1 : OFF_B0) + bLane;
        #pragma unroll
        for (int kk = 0; kk < 4; kk++) {
            int k16 = kc * 4 + kk;
            uint32_t ah[4], al4[4];
            LDSM4(ah, aAddrH + k16 * 32);
            LDSM4(al4, aAddrL + k16 * 32);
            #pragma unroll
            for (int nc = 0; nc < 8; nc++) {
                uint32_t ba = bufBase + nc * (16 * BSTRB) + kk * 32;
                uint32_t bh4[4];
                LDSM4(bh4, ba);
                MMA16816(d[2 * nc],     ah,  bh4[0], bh4[1]);
                MMA16816(d[2 * nc],     al4, bh4[0], bh4[1]);
                MMA16816(d[2 * nc + 1], ah,  bh4[2], bh4[3]);
                MMA16816(d[2 * nc + 1], al4, bh4[2], bh4[3]);
            }
        }
        if (kc + 1 < NCH) {
            uint4* sd = (kc & 1) ? sdst0 : sdst1;
            #pragma unroll
            for (int q = 0; q < 4; q++) sd[q] = rnext[q];
        }
        __syncthreads();
    }

    // ---- spill D -> whbuf (fp32, stride WSTR) ----
    {
        float* whb = (float*)(smc + OFF_WHB);
        int drow = wr * 16 + (l >> 2);
        int dcol = nb0 + (l & 3) * 2;
        #pragma unroll
        for (int nb = 0; nb < 16; nb++) {
            int cb = dcol + nb * 8;
            *(float2*)&whb[drow * WSTR + cb]       = make_float2(d[nb][0], d[nb][1]);
            *(float2*)&whb[(drow + 8) * WSTR + cb] = make_float2(d[nb][2], d[nb][3]);
        }
    }
    __syncthreads();

    // ---- logits: one thread per (u, n, h) ----
    {
        int u = tid >> 6, rem = tid & 63, n = rem & 15, hh = rem >> 4;
        const float* whr = (const float*)(smc + OFF_WHB) + (u * 16 + n) * WSTR + hh * 64;
        const float* ap_ = asrc + hh * 64;
        const float* dp_ = adst + hh * 64;
        float as = 0.f, ad = 0.f;
        #pragma unroll
        for (int c = 0; c < 64; c += 4) {
            float4 v = *(const float4*)&whr[c];
            float4 av = *(const float4*)&ap_[c];
            float4 dv = *(const float4*)&dp_[c];
            as = fmaf(v.x, av.x, fmaf(v.y, av.y, fmaf(v.z, av.z, fmaf(v.w, av.w, as))));
            ad = fmaf(v.x, dv.x, fmaf(v.y, dv.y, fmaf(v.z, dv.z, fmaf(v.w, dv.w, ad))));
        }
        ((float*)(smc + OFF_ES))[u * 64 + n * 4 + hh] = as;
        ((float*)(smc + OFF_ED))[u * 64 + n * 4 + hh] = ad;
    }
    __syncthreads();

    // ---- masked softmax: one thread per (u, i, hh) ----
    {
        int u = tid >> 6, rem = tid & 63, i = rem & 15, hh = rem >> 4;
        const float* es = (const float*)(smc + OFF_ES);
        const float* edp = (const float*)(smc + OFF_ED);
        unsigned m = adjmask(i);
        float ed = edp[u * 64 + i * 4 + hh];
        float eb[NN];
        float mx = -1e30f;
        #pragma unroll
        for (int j = 0; j < NN; j++) {
            eb[j] = -1e30f;
            if ((m >> j) & 1u) {
                float e = ed + es[u * 64 + j * 4 + hh];
                e = e > 0.f ? e : 0.2f * e;
                eb[j] = e;
                mx = fmaxf(mx, e);
            }
        }
        float ssum = 0.f;
        #pragma unroll
        for (int j = 0; j < NN; j++) {
            float a = ((m >> j) & 1u) ? __expf(eb[j] - mx) : 0.f;
            eb[j] = a;
            ssum += a;
        }
        float inv = 1.f / ssum;
        float* al = (float*)(smc + OFF_ALPHA);
        #pragma unroll
        for (int j = 0; j < NN; j++)
            al[u * 1024 + hh * 256 + j * 16 + i] = eb[j] * inv;
    }
    __syncthreads();

    // ---- aggregation: thread (ua, v) -> cols c0..c0+3, f32x2 packed ----
    int ua = tid >> 6, v = tid & 63, c0 = 4 * v, hq = v >> 4;
    ull o2[4][8];
    #pragma unroll
    for (int c = 0; c < 4; c++)
        #pragma unroll
        for (int p = 0; p < 8; p++) o2[c][p] = 0ull;
    {
        const float* au = (const float*)(smc + OFF_ALPHA) + ua * 1024 + hq * 256;
        const float* whu = (const float*)(smc + OFF_WHB) + ua * 16 * WSTR;
        #pragma unroll
        for (int j = 0; j < NN; j++) {
            float4 wv = *(const float4*)&whu[j * WSTR + c0];
            float4 a0 = *(const float4*)&au[j * 16 + 0];
            float4 a1 = *(const float4*)&au[j * 16 + 4];
            float4 a2 = *(const float4*)&au[j * 16 + 8];
            float4 a3 = *(const float4*)&au[j * 16 + 12];
            ull ap[8] = { pk(a0.x,a0.y), pk(a0.z,a0.w), pk(a1.x,a1.y), pk(a1.z,a1.w),
                          pk(a2.x,a2.y), pk(a2.z,a2.w), pk(a3.x,a3.y), pk(a3.z,a3.w) };
            ull wp0 = pk(wv.x, wv.x), wp1 = pk(wv.y, wv.y);
            ull wp2 = pk(wv.z, wv.z), wp3 = pk(wv.w, wv.w);
            #pragma unroll
            for (int p = 0; p < 8; p++) {
                ffma2(o2[0][p], ap[p], wp0);
                ffma2(o2[1][p], ap[p], wp1);
                ffma2(o2[2][p], ap[p], wp2);
                ffma2(o2[3][p], ap[p], wp3);
            }
        }
    }
    __syncthreads();   // whbuf/alpha reads done before overwriting A region

    if (FINAL) {
        float cs[4];
        #pragma unroll
        for (int c = 0; c < 4; c++) {
            float s = 0.f;
            #pragma unroll
            for (int p = 0; p < 8; p++) {
                float lo, hi; upk(o2[c][p], lo, hi);
                s += lo + hi;
            }
            cs[c] = s;
        }
        *(float4*)((float*)(smc + OFF_G4) + ua * 256 + hq * 64 + (c0 & 63)) =
            make_float4(cs[0], cs[1], cs[2], cs[3]);
        __syncthreads();
    } else {
        float4 b4 = *(const float4*)&bb[c0];
        float bbv[4] = { b4.x, b4.y, b4.z, b4.w };
        #pragma unroll
        for (int p = 0; p < 8; p++) {
            float va[4], vb[4];
            #pragma unroll
            for (int c = 0; c < 4; c++) {
                upk(o2[c][p], va[c], vb[c]);
                va[c] = fmaxf(va[c] + bbv[c], 0.f);
                vb[c] = fmaxf(vb[c] + bbv[c], 0.f);
            }
            #pragma unroll
            for (int hf = 0; hf < 2; hf++) {
                const float* src = hf ? vb : va;
                int rowg = ua * 16 + 2 * p + hf;
                unsigned hx[4], lx[4];
                #pragma unroll
                for (int c = 0; c < 4; c++) {
                    float vv = src[c];
                    __half bh = __float2half_rn(vv);
                    __half bl = __float2half_rn(vv - __half2float(bh));
                    hx[c] = (unsigned)__half_as_ushort(bh);
                    lx[c] = (unsigned)__half_as_ushort(bl);
                }
                uint2 ph2, pl2;
                ph2.x = (hx[1] << 16) | hx[0];  ph2.y = (hx[3] << 16) | hx[2];
                pl2.x = (lx[1] << 16) | lx[0];  pl2.y = (lx[3] << 16) | lx[2];
                *(uint2*)(smc + OFF_AH + rowg * ASTRB + c0 * 2) = ph2;
                *(uint2*)(smc + OFF_AL + rowg * ASTRB + c0 * 2) = pl2;
            }
        }
        __syncthreads();
    }
}

__global__ void __launch_bounds__(512, 1) gat_mma_kernel(
    const float* __restrict__ x,
    const float* __restrict__ w_in, const float* __restrict__ b_in,
    const float* __restrict__ as0, const float* __restrict__ ad0,
    const float* __restrict__ bb0,
    const float* __restrict__ as1, const float* __restrict__ ad1,
    const float* __restrict__ bb1,
    const float* __restrict__ as2, const float* __restrict__ ad2,
    const float* __restrict__ bb2,
    const float* __restrict__ w1, const float* __restrict__ b1,
    const float* __restrict__ lng, const float* __restrict__ lnb,
    const float* __restrict__ w2, const float* __restrict__ b2,
    float* __restrict__ out)
{
    extern __shared__ char smc[];
    uint32_t smb = smem_u32(smc);
    int tid = threadIdx.x;
    long item0 = (long)blockIdx.x * 8;

    // stage x: 8 items * 256 floats into (pre-layer0-dead) B0 region
    float* xs = (float*)(smc + OFF_XS);
    #pragma unroll
    for (int q = 0; q < 4; q++)
        xs[q * 512 + tid] = x[item0 * 256 + q * 512 + tid];
    __syncthreads();

    // input linear -> A (fp16 hi/lo), thread = (u = tid>>6, f = tid&63)
    {
        int u = tid >> 6, f = tid & 63;
        const float* xu = xs + u * 256;
        float acc[NN];
        #pragma unroll
        for (int nn = 0; nn < NN; nn++) acc[nn] = 0.f;
        #pragma unroll
        for (int c = 0; c < 16; c++) {
            float wv = w_in[c * 64 + f];
            #pragma unroll
            for (int nn = 0; nn < NN; nn++)
                acc[nn] = fmaf(xu[c * 16 + nn], wv, acc[nn]);
        }
        float bv = b_in[f];
        #pragma unroll
        for (int nn = 0; nn < NN; nn++) {
            float vv = fmaxf(acc[nn] + bv, 0.f);
            __half bh = __float2half_rn(vv);
            __half bl = __float2half_rn(vv - __half2float(bh));
            int row = u * 16 + nn;
            *(__half*)(smc + OFF_AH + row * ASTRB + f * 2) = bh;
            *(__half*)(smc + OFF_AL + row * ASTRB + f * 2) = bl;
        }
    }
    __syncthreads();

    gat_layer<64,  false>(smc, smb, tid, g_WTh,         as0, ad0, bb0);
    gat_layer<256, false>(smc, smb, tid, g_WTh + 16384, as1, ad1, bb1);
    gat_layer<256, true >(smc, smb, tid, g_WTh + 81920, as2, ad2, bb2);

    // pooled g[c] = mean over nodes+heads + bb2
    {
        int u = tid >> 6, cc = tid & 63;
        const float* g4 = (const float*)(smc + OFF_G4) + u * 256;
        float sg = g4[cc] + g4[64 + cc] + g4[128 + cc] + g4[192 + cc];
        ((float*)(smc + OFF_G))[u * 64 + cc] = sg * (1.0f / 64.0f) + bb2[cc];
    }
    __syncthreads();

    // MLP1 (64->128) + LN + relu; thread covers items up, up+4
    {
        int fy = tid & 127, up = tid >> 7;
        int ua = up, ub = up + 4;
        const float* ga_ = (const float*)(smc + OFF_G) + ua * 64;
        const float* gb_ = (const float*)(smc + OFF_G) + ub * 64;
        float va = b1[fy], vb = va;
        #pragma unroll 4
        for (int c = 0; c < 64; c += 4) {
            float4 ga = *(const float4*)&ga_[c];
            float4 gb = *(const float4*)&gb_[c];
            float w0 = w1[(c + 0) * 128 + fy];
            float wA = w1[(c + 1) * 128 + fy];
            float wB = w1[(c + 2) * 128 + fy];
            float wC = w1[(c + 3) * 128 + fy];
            va = fmaf(ga.x, w0, fmaf(ga.y, wA, fmaf(ga.z, wB, fmaf(ga.w, wC, va))));
            vb = fmaf(gb.x, w0, fmaf(gb.y, wA, fmaf(gb.z, wB, fmaf(gb.w, wC, vb))));
        }
        float* red = (float*)(smc + OFF_RED);
        float sa = va, sb = vb;
        #pragma unroll
        for (int off = 16; off; off >>= 1) {
            sa += __shfl_xor_sync(0xffffffffu, sa, off);
            sb += __shfl_xor_sync(0xffffffffu, sb, off);
        }
        int wi = (tid >> 5) & 3;
        if ((tid & 31) == 0) { red[ua * 8 + wi] = sa; red[ub * 8 + wi] = sb; }
        __syncthreads();
        float mua = (red[ua * 8] + red[ua * 8 + 1] + red[ua * 8 + 2] + red[ua * 8 + 3]) * (1.f / 128.f);
        float mub = (red[ub * 8] + red[ub * 8 + 1] + red[ub * 8 + 2] + red[ub * 8 + 3]) * (1.f / 128.f);
        float da = va - mua, db = vb - mub;
        float qa = da * da, qb = db * db;
        #pragma unroll
        for (int off = 16; off; off >>= 1) {
            qa += __shfl_xor_sync(0xffffffffu, qa, off);
            qb += __shfl_xor_sync(0xffffffffu, qb, off);
        }
        if ((tid & 31) == 0) { red[ua * 8 + 4 + wi] = qa; red[ub * 8 + 4 + wi] = qb; }
        __syncthreads();
        float vara = (red[ua * 8 + 4] + red[ua * 8 + 5] + red[ua * 8 + 6] + red[ua * 8 + 7]) * (1.f / 128.f);
        float varb = (red[ub * 8 + 4] + red[ub * 8 + 5] + red[ub * 8 + 6] + red[ub * 8 + 7]) * (1.f / 128.f);
        float gv = lng[fy], bv = lnb[fy];
        float* yv = (float*)(smc + OFF_Y);
        yv[ua * 132 + fy] = fmaxf(da * rsqrtf(vara + 1e-5f) * gv + bv, 0.f);
        yv[ub * 132 + fy] = fmaxf(db * rsqrtf(varb + 1e-5f) * gv + bv, 0.f);
    }
    __syncthreads();

    // MLP2 (128->256): thread = (pr = tid>>8 -> items 4pr..4pr+3, col = tid&255)
    {
        int col = tid & 255, pr = tid >> 8;
        const float* yv = (const float*)(smc + OFF_Y) + pr * 4 * 132;
        float a0 = b2[col], a1 = a0, a2 = a0, a3 = a0;
        #pragma unroll 4
        for (int f = 0; f < 128; f += 4) {
            float4 y0 = *(const float4*)&yv[0 * 132 + f];
            float4 y1 = *(const float4*)&yv[1 * 132 + f];
            float4 y2 = *(const float4*)&yv[2 * 132 + f];
            float4 y3 = *(const float4*)&yv[3 * 132 + f];
            float w0 = w2[(f + 0) * 256 + col];
            float wA = w2[(f + 1) * 256 + col];
            float wB = w2[(f + 2) * 256 + col];
            float wC = w2[(f + 3) * 256 + col];
            a0 = fmaf(y0.x, w0, fmaf(y0.y, wA, fmaf(y0.z, wB, fmaf(y0.w, wC, a0))));
            a1 = fmaf(y1.x, w0, fmaf(y1.y, wA, fmaf(y1.z, wB, fmaf(y1.w, wC, a1))));
            a2 = fmaf(y2.x, w0, fmaf(y2.y, wA, fmaf(y2.z, wB, fmaf(y2.w, wC, a2))));
            a3 = fmaf(y3.x, w0, fmaf(y3.y, wA, fmaf(y3.z, wB, fmaf(y3.w, wC, a3))));
        }
        out[(item0 + 4 * pr + 0) * 256 + col] = a0;
        out[(item0 + 4 * pr + 1) * 256 + col] = a1;
        out[(item0 + 4 * pr + 2) * 256 + col] = a2;
        out[(item0 + 4 * pr + 3) * 256 + col] = a3;
    }
}

extern "C" void kernel_launch(void* const* d_in, const int* in_sizes, int n_in,
                              void* d_out, int out_size)
{
    const float* x    = (const float*)d_in[0];
    const float* w_in = (const float*)d_in[1];
    const float* b_in = (const float*)d_in[2];
    const float* W0   = (const float*)d_in[3];
    const float* as0  = (const float*)d_in[4];
    const float* ad0  = (const float*)d_in[5];
    const float* bb0  = (const float*)d_in[6];
    const float* W1   = (const float*)d_in[7];
    const float* as1  = (const float*)d_in[8];
    const float* ad1  = (const float*)d_in[9];
    const float* bb1  = (const float*)d_in[10];
    const float* W2   = (const float*)d_in[11];
    const float* as2  = (const float*)d_in[12];
    const float* ad2  = (const float*)d_in[13];
    const float* bb2  = (const float*)d_in[14];
    const float* w1   = (const float*)d_in[15];
    const float* b1   = (const float*)d_in[16];
    const float* lng  = (const float*)d_in[17];
    const float* lnb  = (const float*)d_in[18];
    const float* w2   = (const float*)d_in[19];
    const float* b2   = (const float*)d_in[20];
    float* out = (float*)d_out;

    int B = out_size / 256;        // 16384
    int grid = B / 8;              // 8 graphs per block

    prep_kernel<<<576, 256>>>(W0, W1, W2);

    cudaFuncSetAttribute(gat_mma_kernel,
                         cudaFuncAttributeMaxDynamicSharedMemorySize, SMEM_BYTES);
    gat_mma_kernel<<<grid, 512, SMEM_BYTES>>>(
        x, w_in, b_in,
        as0, ad0, bb0, as1, ad1, bb1, as2, ad2, bb2,
        w1, b1, lng, lnb, w2, b2, out);
}